// round 7
// baseline (speedup 1.0000x reference)
#include <cuda_runtime.h>
#include <cuda_bf16.h>

// ---------------- problem constants ----------------
#define B_    32
#define CIN   128
#define HW    56
#define COUT  256
#define NE    4
#define RR    16
#define SPAT  (HW*HW)          // 3136
#define SAMP_K (COUT*CIN*9)    // 294912 weights per expert

// ---------------- tiny scratch only (512 B) ----------------
__device__ float g_routing[B_*NE];

// ---------------- f32x2 packed helpers ----------------
__device__ __forceinline__ unsigned long long pk2(float a, float b) {
    unsigned long long r;
    asm("mov.b64 %0, {%1, %2};" : "=l"(r) : "f"(a), "f"(b));
    return r;
}
__device__ __forceinline__ void upk2(unsigned long long v, float& lo, float& hi) {
    asm("mov.b64 {%0, %1}, %2;" : "=f"(lo), "=f"(hi) : "l"(v));
}
__device__ __forceinline__ void ffma2(unsigned long long& d,
                                      unsigned long long a,
                                      unsigned long long b) {
    asm("fma.rn.f32x2 %0, %1, %2, %0;" : "+l"(d) : "l"(a), "l"(b));
}

// ============================================================
// Kernel 1: GAP -> MLP -> softmax(logits/30) -> g_routing
// one block per sample; 8 warps stride over 128 channels.
// ============================================================
__global__ void __launch_bounds__(256) router_kernel(
    const float* __restrict__ x,
    const float* __restrict__ w1, const float* __restrict__ b1,
    const float* __restrict__ w2, const float* __restrict__ b2)
{
    int b    = blockIdx.x;
    int tid  = threadIdx.x;
    int warp = tid >> 5, lane = tid & 31;

    __shared__ float gap[CIN];
    __shared__ float hbuf[RR];

    for (int c = warp; c < CIN; c += 8) {
        const float* p = x + ((size_t)b*CIN + c)*SPAT;
        float s = 0.f;
        for (int i = lane; i < SPAT; i += 32) s += p[i];
        #pragma unroll
        for (int o = 16; o; o >>= 1) s += __shfl_xor_sync(0xffffffffu, s, o);
        if (lane == 0) gap[c] = s * (1.0f/(float)SPAT);
    }
    __syncthreads();

    if (tid < RR) {
        float s = b1[tid];
        const float* wr = w1 + tid*CIN;
        #pragma unroll 8
        for (int i = 0; i < CIN; i++) s += gap[i]*wr[i];
        hbuf[tid] = fmaxf(s, 0.f);
    }
    __syncthreads();

    if (tid == 0) {
        float lg[NE];
        float mx = -1e30f;
        #pragma unroll
        for (int e = 0; e < NE; e++) {
            float s = b2[e];
            #pragma unroll
            for (int r = 0; r < RR; r++) s += hbuf[r]*w2[e*RR + r];
            lg[e] = s * (1.0f/30.0f);
            mx = fmaxf(mx, lg[e]);
        }
        float den = 0.f;
        #pragma unroll
        for (int e = 0; e < NE; e++) { lg[e] = expf(lg[e]-mx); den += lg[e]; }
        float inv = 1.0f/den;
        #pragma unroll
        for (int e = 0; e < NE; e++) g_routing[b*NE + e] = lg[e]*inv;
    }
}

// ============================================================
// Kernel 2: direct conv, fp32 with f32x2 packed FMA.
// Expert mix is FUSED into the weight-staging stage: convs (18.9MB)
// is L2-resident, each staged weight = sum_e r[b,e]*convs[e][...].
// Block tile: 32 oc x 4 rows x 56 cols, one sample.
// Thread tile: 4 oc (2 f32x2 pairs) x 7 px.
// grid (8, 14, 32)
// ============================================================
#define OCT  32
#define RT   4
#define CIC  8
#define IN_W 58
#define IN_H 6

__global__ void __launch_bounds__(256, 2) dyconv_kernel(
    const float* __restrict__ x,
    const float* __restrict__ convs,
    float* __restrict__ out)
{
    __shared__ __align__(16) float in_s[CIC*IN_H*IN_W];   // 2784 floats
    __shared__ __align__(16) float w_s[CIC*9*OCT];        // 2304 floats, [ci][tap][oc]

    int tid  = threadIdx.x;
    int ocb  = blockIdx.x;          // 0..7
    int rb   = blockIdx.y;          // 0..13
    int b    = blockIdx.z;          // 0..31
    int oc0  = ocb*OCT;
    int r0   = rb*RT;

    int warp = tid >> 5;            // 0..7 -> 4-oc subgroup
    int lane = tid & 31;
    int row  = lane >> 3;           // 0..3
    int colb = (lane & 7)*7;        // 0,7,...,49

    // per-sample routing weights (broadcast L2 loads)
    float r0w = g_routing[b*NE+0];
    float r1w = g_routing[b*NE+1];
    float r2w = g_routing[b*NE+2];
    float r3w = g_routing[b*NE+3];

    unsigned long long acc[2][7];
    #pragma unroll
    for (int i = 0; i < 2; i++)
        #pragma unroll
        for (int p = 0; p < 7; p++) acc[i][p] = 0ULL;

    const float* xb = x + (size_t)b*CIN*SPAT;

    for (int ci0 = 0; ci0 < CIN; ci0 += CIC) {
        __syncthreads();
        // ---- stage input halo tile: [CIC][6][58], zero-padded borders
        for (int l = tid; l < CIC*IN_H*IN_W; l += 256) {
            int ci  = l / (IN_H*IN_W);
            int rem = l - ci*(IN_H*IN_W);
            int rr2 = rem / IN_W;
            int cc  = rem - rr2*IN_W;
            int gh  = r0 - 1 + rr2;
            int gw  = cc - 1;
            float v = 0.f;
            if ((unsigned)gh < HW && (unsigned)gw < HW)
                v = xb[((ci0+ci)*HW + gh)*HW + gw];
            in_s[l] = v;
        }
        // ---- stage + MIX weights: w_s[(ci*9+tap)*32 + oc]
        //      = sum_e routing[e] * convs[e][oc0+i][ci0+c][tap]
        for (int l = tid; l < OCT*CIC*9; l += 256) {
            int i   = l / (CIC*9);
            int rem = l - i*(CIC*9);
            int c   = rem / 9;
            int t   = rem - c*9;
            size_t off = ((size_t)(oc0+i)*CIN + (ci0 + c))*9 + t;
            float v = r0w*convs[off]
                    + r1w*convs[(size_t)SAMP_K   + off]
                    + r2w*convs[(size_t)2*SAMP_K + off]
                    + r3w*convs[(size_t)3*SAMP_K + off];
            w_s[(c*9 + t)*OCT + i] = v;
        }
        __syncthreads();

        #pragma unroll
        for (int ci = 0; ci < CIC; ci++) {
            const float* wb_ = &w_s[ci*9*OCT + warp*4];
            #pragma unroll
            for (int ky = 0; ky < 3; ky++) {
                const float* ir = &in_s[ci*(IN_H*IN_W) + (row+ky)*IN_W + colb];
                unsigned long long xd[9];
                #pragma unroll
                for (int d2 = 0; d2 < 9; d2++) {
                    float xv = ir[d2];
                    xd[d2] = pk2(xv, xv);          // duplicate into both f32x2 lanes
                }
                #pragma unroll
                for (int kx = 0; kx < 3; kx++) {
                    // warp-uniform float4 -> broadcast LDS.128 (free)
                    const float4 wv = *(const float4*)&wb_[(ky*3 + kx)*OCT];
                    unsigned long long wp0 = pk2(wv.x, wv.y);   // oc+0, oc+1
                    unsigned long long wp1 = pk2(wv.z, wv.w);   // oc+2, oc+3
                    #pragma unroll
                    for (int p = 0; p < 7; p++) {
                        ffma2(acc[0][p], wp0, xd[p+kx]);
                        ffma2(acc[1][p], wp1, xd[p+kx]);
                    }
                }
            }
        }
    }

    // ---- epilogue: unpack pairs, scatter per oc
    int orow = r0 + row;
    float* ob = out + (((size_t)b*COUT + oc0 + warp*4)*HW + orow)*HW + colb;
    #pragma unroll
    for (int p = 0; p < 7; p++) {
        float a0, a1, a2, a3;
        upk2(acc[0][p], a0, a1);
        upk2(acc[1][p], a2, a3);
        ob[p]            = a0;
        ob[SPAT + p]     = a1;
        ob[2*SPAT + p]   = a2;
        ob[3*SPAT + p]   = a3;
    }
}

// ============================================================
extern "C" void kernel_launch(void* const* d_in, const int* in_sizes, int n_in,
                              void* d_out, int out_size)
{
    const float* x     = (const float*)d_in[0];   // [32,128,56,56]
    const float* convs = (const float*)d_in[1];   // [4,256,128,3,3]
    const float* w1    = (const float*)d_in[2];   // [16,128]
    const float* b1    = (const float*)d_in[3];   // [16]
    const float* w2    = (const float*)d_in[4];   // [4,16]
    const float* b2    = (const float*)d_in[5];   // [4]
    float* out = (float*)d_out;                   // [32,256,56,56]

    router_kernel<<<B_, 256>>>(x, w1, b1, w2, b2);
    dyconv_kernel<<<dim3(COUT/OCT, HW/RT, B_), 256>>>(x, convs, out);
}

// round 9
// speedup vs baseline: 1.2814x; 1.2814x over previous
#include <cuda_runtime.h>
#include <cuda_bf16.h>

// ---------------- problem constants ----------------
#define B_    32
#define CIN   128
#define HW    56
#define COUT  256
#define NE    4
#define RR    16
#define SPAT  (HW*HW)          // 3136
#define SAMP_K (COUT*CIN*9)    // 294912 weights per expert

// ---------------- tiny scratch only (512 B) ----------------
__device__ float g_routing[B_*NE];

// ---------------- f32x2 packed helpers ----------------
__device__ __forceinline__ unsigned long long pk2(float a, float b) {
    unsigned long long r;
    asm("mov.b64 %0, {%1, %2};" : "=l"(r) : "f"(a), "f"(b));
    return r;
}
__device__ __forceinline__ void upk2(unsigned long long v, float& lo, float& hi) {
    asm("mov.b64 {%0, %1}, %2;" : "=f"(lo), "=f"(hi) : "l"(v));
}
__device__ __forceinline__ void ffma2(unsigned long long& d,
                                      unsigned long long a,
                                      unsigned long long b) {
    asm("fma.rn.f32x2 %0, %1, %2, %0;" : "+l"(d) : "l"(a), "l"(b));
}

// ============================================================
// Kernel 1: GAP -> MLP -> softmax(logits/30) -> g_routing
// ============================================================
__global__ void __launch_bounds__(256) router_kernel(
    const float* __restrict__ x,
    const float* __restrict__ w1, const float* __restrict__ b1,
    const float* __restrict__ w2, const float* __restrict__ b2)
{
    int b    = blockIdx.x;
    int tid  = threadIdx.x;
    int warp = tid >> 5, lane = tid & 31;

    __shared__ float gap[CIN];
    __shared__ float hbuf[RR];

    for (int c = warp; c < CIN; c += 8) {
        const float* p = x + ((size_t)b*CIN + c)*SPAT;
        float s = 0.f;
        for (int i = lane; i < SPAT; i += 32) s += p[i];
        #pragma unroll
        for (int o = 16; o; o >>= 1) s += __shfl_xor_sync(0xffffffffu, s, o);
        if (lane == 0) gap[c] = s * (1.0f/(float)SPAT);
    }
    __syncthreads();

    if (tid < RR) {
        float s = b1[tid];
        const float* wr = w1 + tid*CIN;
        #pragma unroll 8
        for (int i = 0; i < CIN; i++) s += gap[i]*wr[i];
        hbuf[tid] = fmaxf(s, 0.f);
    }
    __syncthreads();

    if (tid == 0) {
        float lg[NE];
        float mx = -1e30f;
        #pragma unroll
        for (int e = 0; e < NE; e++) {
            float s = b2[e];
            #pragma unroll
            for (int r = 0; r < RR; r++) s += hbuf[r]*w2[e*RR + r];
            lg[e] = s * (1.0f/30.0f);
            mx = fmaxf(mx, lg[e]);
        }
        float den = 0.f;
        #pragma unroll
        for (int e = 0; e < NE; e++) { lg[e] = expf(lg[e]-mx); den += lg[e]; }
        float inv = 1.0f/den;
        #pragma unroll
        for (int e = 0; e < NE; e++) g_routing[b*NE + e] = lg[e]*inv;
    }
}

// ============================================================
// Kernel 2: direct conv, fp32 f32x2 packed FMA, expert mix fused
// into weight staging (convs is L2-resident).
// Block tile: 64 oc x 4 rows x 56 cols, one sample.
// Thread tile: 8 oc (4 f32x2 pairs) x 7 px.
//   warp -> 8-oc subgroup; lane = (row<<3)|colgroup.
// Conflict-free smem:
//   input  pitch 72  -> bank = (8*row + 7*cg) mod 32, all distinct
//   weight pitch 68  -> STS order (i_lo,j,i_hi) gives distinct banks,
//                       68*j + warp*8 is 16B aligned for LDS.128 reads
// grid (4, 14, 32)
// ============================================================
#define OCT   64
#define RT    4
#define CIC   8
#define IN_W  72
#define IN_H  6
#define WPITCH 68
#define WTAPS  (CIC*9)         // 72 taps per chunk per oc

__global__ void __launch_bounds__(256, 2) dyconv_kernel(
    const float* __restrict__ x,
    const float* __restrict__ convs,
    float* __restrict__ out)
{
    __shared__ __align__(16) float in_s[CIC*IN_H*IN_W];    // 3456 floats
    __shared__ __align__(16) float w_s[WTAPS*WPITCH];      // 4896 floats, [j][oc(+pad)]

    int tid  = threadIdx.x;
    int ocb  = blockIdx.x;          // 0..3
    int rb   = blockIdx.y;          // 0..13
    int b    = blockIdx.z;          // 0..31
    int oc0  = ocb*OCT;
    int r0   = rb*RT;

    int warp = tid >> 5;            // 0..7 -> 8-oc subgroup
    int lane = tid & 31;
    int row  = lane >> 3;           // 0..3
    int colb = (lane & 7)*7;        // 0,7,...,49

    // per-sample routing weights (broadcast loads)
    float r0w = g_routing[b*NE+0];
    float r1w = g_routing[b*NE+1];
    float r2w = g_routing[b*NE+2];
    float r3w = g_routing[b*NE+3];

    unsigned long long acc[4][7];
    #pragma unroll
    for (int i = 0; i < 4; i++)
        #pragma unroll
        for (int p = 0; p < 7; p++) acc[i][p] = 0ULL;

    const float* xb = x + (size_t)b*CIN*SPAT;

    for (int ci0 = 0; ci0 < CIN; ci0 += CIC) {
        __syncthreads();
        // ---- stage input halo tile: [CIC][6][58] into pitch-72 rows
        for (int l = tid; l < CIC*IN_H*58; l += 256) {
            int ci  = l / (IN_H*58);
            int rem = l - ci*(IN_H*58);
            int rr2 = rem / 58;
            int cc  = rem - rr2*58;
            int gh  = r0 - 1 + rr2;
            int gw  = cc - 1;
            float v = 0.f;
            if ((unsigned)gh < HW && (unsigned)gw < HW)
                v = xb[((ci0+ci)*HW + gh)*HW + gw];
            in_s[ci*(IN_H*IN_W) + rr2*IN_W + cc] = v;
        }
        // ---- stage + MIX weights into w_s[j*68 + i]
        //      i_lo = idx&3, j = (idx>>2)%72, i_hi = (idx>>2)/72
        //      -> conflict-free STS, ~4-sector coalesced LDG
        for (int idx = tid; idx < OCT*WTAPS; idx += 256) {
            int i_lo = idx & 3;
            int tmp  = idx >> 2;
            int j    = tmp % WTAPS;
            int i_hi = tmp / WTAPS;
            int i    = (i_hi << 2) | i_lo;
            size_t off = (size_t)(oc0 + i)*(CIN*9) + (size_t)ci0*9 + j;
            float v = r0w*convs[off]
                    + r1w*convs[(size_t)SAMP_K   + off]
                    + r2w*convs[(size_t)2*SAMP_K + off]
                    + r3w*convs[(size_t)3*SAMP_K + off];
            w_s[j*WPITCH + i] = v;
        }
        __syncthreads();

        #pragma unroll 2
        for (int ci = 0; ci < CIC; ci++) {
            #pragma unroll
            for (int ky = 0; ky < 3; ky++) {
                const float* ir = &in_s[ci*(IN_H*IN_W) + (row+ky)*IN_W + colb];
                unsigned long long xd[9];
                #pragma unroll
                for (int d2 = 0; d2 < 9; d2++) {
                    float xv = ir[d2];
                    xd[d2] = pk2(xv, xv);          // duplicate into both f32x2 lanes
                }
                #pragma unroll
                for (int kx = 0; kx < 3; kx++) {
                    int j = ci*9 + ky*3 + kx;
                    // warp-uniform float4 pair -> broadcast LDS.128 (16B aligned)
                    const float4 wa = *(const float4*)&w_s[j*WPITCH + warp*8];
                    const float4 wb = *(const float4*)&w_s[j*WPITCH + warp*8 + 4];
                    unsigned long long wp0 = pk2(wa.x, wa.y);   // oc+0, oc+1
                    unsigned long long wp1 = pk2(wa.z, wa.w);   // oc+2, oc+3
                    unsigned long long wp2 = pk2(wb.x, wb.y);   // oc+4, oc+5
                    unsigned long long wp3 = pk2(wb.z, wb.w);   // oc+6, oc+7
                    #pragma unroll
                    for (int p = 0; p < 7; p++) {
                        ffma2(acc[0][p], wp0, xd[p+kx]);
                        ffma2(acc[1][p], wp1, xd[p+kx]);
                        ffma2(acc[2][p], wp2, xd[p+kx]);
                        ffma2(acc[3][p], wp3, xd[p+kx]);
                    }
                }
            }
        }
    }

    // ---- epilogue: unpack pairs, scatter per oc
    int orow = r0 + row;
    float* ob = out + (((size_t)b*COUT + oc0 + warp*8)*SPAT) + orow*HW + colb;
    #pragma unroll
    for (int pr = 0; pr < 4; pr++) {
        #pragma unroll
        for (int p = 0; p < 7; p++) {
            float a0, a1;
            upk2(acc[pr][p], a0, a1);
            ob[(size_t)(2*pr  )*SPAT + p] = a0;
            ob[(size_t)(2*pr+1)*SPAT + p] = a1;
        }
    }
}

// ============================================================
extern "C" void kernel_launch(void* const* d_in, const int* in_sizes, int n_in,
                              void* d_out, int out_size)
{
    const float* x     = (const float*)d_in[0];   // [32,128,56,56]
    const float* convs = (const float*)d_in[1];   // [4,256,128,3,3]
    const float* w1    = (const float*)d_in[2];   // [16,128]
    const float* b1    = (const float*)d_in[3];   // [16]
    const float* w2    = (const float*)d_in[4];   // [4,16]
    const float* b2    = (const float*)d_in[5];   // [4]
    float* out = (float*)d_out;                   // [32,256,56,56]

    router_kernel<<<B_, 256>>>(x, w1, b1, w2, b2);
    dyconv_kernel<<<dim3(COUT/OCT, HW/RT, B_), 256>>>(x, convs, out);
}

// round 12
// speedup vs baseline: 1.5256x; 1.1906x over previous
#include <cuda_runtime.h>
#include <cuda_bf16.h>
#include <cstdint>

// ---------------- problem constants ----------------
#define B_    32
#define CIN   128
#define HW    56
#define COUT  256
#define NE    4
#define RR    16
#define SPAT  (HW*HW)          // 3136
#define SAMP_K (COUT*CIN*9)    // 294912 weights per expert

// conv tiling
#define OCT   64               // oc per block
#define RT    4                // output rows per block
#define CIC   4                // cin per chunk
#define NCH   (CIN/CIC)        // 32 chunks
#define IN_W  72               // input smem pitch (bank: (8r+7c)%32 distinct)
#define IN_H  6
#define IN_SZ (CIC*IN_H*IN_W)  // 1728
#define WT_J  (CIC*9)          // 36 taps per chunk
#define W_SZ  (WT_J*OCT)       // 2304

// ---------------- device scratch ----------------
__device__ float g_routing[B_*NE];
// mixed kernels, layout [b][ocb(4)][chunk(32)][tap(36)][oc(64)]
__device__ float g_kern[(size_t)B_*SAMP_K];

// ---------------- f32x2 packed helpers ----------------
__device__ __forceinline__ unsigned long long pk2(float a, float b) {
    unsigned long long r;
    asm("mov.b64 %0, {%1, %2};" : "=l"(r) : "f"(a), "f"(b));
    return r;
}
__device__ __forceinline__ void upk2(unsigned long long v, float& lo, float& hi) {
    asm("mov.b64 {%0, %1}, %2;" : "=f"(lo), "=f"(hi) : "l"(v));
}
__device__ __forceinline__ void ffma2(unsigned long long& d,
                                      unsigned long long a,
                                      unsigned long long b) {
    asm("fma.rn.f32x2 %0, %1, %2, %0;" : "+l"(d) : "l"(a), "l"(b));
}

// ---------------- cp.async helpers ----------------
__device__ __forceinline__ void cpa16(uint32_t dst, const float* src) {
    asm volatile("cp.async.cg.shared.global [%0], [%1], 16;" :: "r"(dst), "l"(src));
}
#define CP_COMMIT() asm volatile("cp.async.commit_group;" ::: "memory")
#define CP_WAIT1()  asm volatile("cp.async.wait_group 1;" ::: "memory")
#define CP_WAIT0()  asm volatile("cp.async.wait_group 0;" ::: "memory")

// ============================================================
// Kernel 1: GAP -> MLP -> softmax(logits/30) -> g_routing
// ============================================================
__global__ void __launch_bounds__(256) router_kernel(
    const float* __restrict__ x,
    const float* __restrict__ w1, const float* __restrict__ b1,
    const float* __restrict__ w2, const float* __restrict__ b2)
{
    int b    = blockIdx.x;
    int tid  = threadIdx.x;
    int warp = tid >> 5, lane = tid & 31;

    __shared__ float gap[CIN];
    __shared__ float hbuf[RR];

    for (int c = warp; c < CIN; c += 8) {
        const float* p = x + ((size_t)b*CIN + c)*SPAT;
        float s = 0.f;
        for (int i = lane; i < SPAT; i += 32) s += p[i];
        #pragma unroll
        for (int o = 16; o; o >>= 1) s += __shfl_xor_sync(0xffffffffu, s, o);
        if (lane == 0) gap[c] = s * (1.0f/(float)SPAT);
    }
    __syncthreads();

    if (tid < RR) {
        float s = b1[tid];
        const float* wr = w1 + tid*CIN;
        #pragma unroll 8
        for (int i = 0; i < CIN; i++) s += gap[i]*wr[i];
        hbuf[tid] = fmaxf(s, 0.f);
    }
    __syncthreads();

    if (tid == 0) {
        float lg[NE];
        float mx = -1e30f;
        #pragma unroll
        for (int e = 0; e < NE; e++) {
            float s = b2[e];
            #pragma unroll
            for (int r = 0; r < RR; r++) s += hbuf[r]*w2[e*RR + r];
            lg[e] = s * (1.0f/30.0f);
            mx = fmaxf(mx, lg[e]);
        }
        float den = 0.f;
        #pragma unroll
        for (int e = 0; e < NE; e++) { lg[e] = expf(lg[e]-mx); den += lg[e]; }
        float inv = 1.0f/den;
        #pragma unroll
        for (int e = 0; e < NE; e++) g_routing[b*NE + e] = lg[e]*inv;
    }
}

// ============================================================
// Kernel 2: expert mix + layout transform.
// g_kern[b][ocb][chunk][j][oc] = sum_e r[b,e]*convs[e][ocb*64+oc][chunk*4+ci][t]
//   (j = ci_local*9 + t)
// grid (chunk=32, ocb=4, b=32), 256 thr. smem transpose for coalescing.
// ============================================================
__global__ void __launch_bounds__(256) mix_kernel(const float* __restrict__ convs)
{
    __shared__ float trans[WT_J*65];   // [jj][oc], pitch 65

    int chunk = blockIdx.x;
    int ocb   = blockIdx.y;
    int b     = blockIdx.z;
    int tid   = threadIdx.x;

    float r0w = g_routing[b*NE+0];
    float r1w = g_routing[b*NE+1];
    float r2w = g_routing[b*NE+2];
    float r3w = g_routing[b*NE+3];

    // read coalesced along [ci][t] runs, mix, store transposed
    for (int rid = tid; rid < W_SZ; rid += 256) {
        int oc_r = rid / WT_J;
        int jj   = rid - oc_r*WT_J;
        size_t off = (size_t)(ocb*OCT + oc_r)*(CIN*9) + chunk*WT_J + jj;
        float v = r0w*convs[off]
                + r1w*convs[(size_t)SAMP_K   + off]
                + r2w*convs[(size_t)2*SAMP_K + off]
                + r3w*convs[(size_t)3*SAMP_K + off];
        trans[jj*65 + oc_r] = v;
    }
    __syncthreads();

    // write coalesced [j][oc]
    float* dst = g_kern + (((size_t)b*4 + ocb)*NCH + chunk)*W_SZ;
    for (int wid = tid; wid < W_SZ; wid += 256) {
        int j    = wid >> 6;          // /64
        int oc_w = wid & 63;
        dst[wid] = trans[j*65 + oc_w];
    }
}

// ============================================================
// Kernel 3: direct conv, fp32 f32x2 packed FMA.
// cp.async double-buffered staging of input + premixed weights.
// Block tile: 64 oc x 4 rows x 56 cols, one sample.
// Thread tile: 8 oc (4 f32x2 pairs) x 7 px.
// grid (4, 14, 32)
// ============================================================
__global__ void __launch_bounds__(256, 2) dyconv_kernel(
    const float* __restrict__ x, float* __restrict__ out)
{
    __shared__ __align__(16) float in_s[2][IN_SZ];   // 2x1728
    __shared__ __align__(16) float w_s[2][W_SZ];     // 2x2304, [j][oc]

    int tid  = threadIdx.x;
    int ocb  = blockIdx.x;          // 0..3
    int rb   = blockIdx.y;          // 0..13
    int b    = blockIdx.z;          // 0..31
    int oc0  = ocb*OCT;
    int r0   = rb*RT;

    int warp = tid >> 5;            // 0..7 -> 8-oc subgroup
    int lane = tid & 31;
    int row  = lane >> 3;           // 0..3
    int colb = (lane & 7)*7;        // 0,7,...,49

    const float* xb = x + (size_t)b*CIN*SPAT;
    const float* kb = g_kern + (((size_t)b*4 + ocb)*NCH)*W_SZ;

    uint32_t in_base[2], w_base[2];
    in_base[0] = (uint32_t)__cvta_generic_to_shared(&in_s[0][0]);
    in_base[1] = (uint32_t)__cvta_generic_to_shared(&in_s[1][0]);
    w_base[0]  = (uint32_t)__cvta_generic_to_shared(&w_s[0][0]);
    w_base[1]  = (uint32_t)__cvta_generic_to_shared(&w_s[1][0]);

    // zero both input buffers once (borders + OOB rows stay zero; their
    // positions depend only on rb, so they remain valid across chunks)
    for (int l = tid; l < 2*IN_SZ; l += 256) ((float*)in_s)[l] = 0.f;
    __syncthreads();

    // ---- staging lambda-ish macro via inline code --------------
    // input: interior 56 floats of each in-range row as 14x cp.async(16B)
    //        smem layout: [ci][rr][pad3 | halo | 56 interior | halo | pad]
    //        interior starts at col 4 (16B aligned with pitch 72).
    // weights: contiguous 2304 floats = 576x 16B.
    #define STAGE(ck, buf) do {                                               \
        int _c = (ck);                                                        \
        for (int t = tid; t < CIC*IN_H*14; t += 256) {                        \
            int ci  = t / (IN_H*14);                                          \
            int rem = t - ci*(IN_H*14);                                       \
            int rr  = rem / 14;                                               \
            int seg = rem - rr*14;                                            \
            int gh  = r0 - 1 + rr;                                            \
            if ((unsigned)gh < HW) {                                          \
                uint32_t d = in_base[buf] + ((ci*IN_H + rr)*IN_W + 4 + seg*4)*4; \
                const float* s = xb + ((size_t)(_c*CIC + ci)*HW + gh)*HW + seg*4; \
                cpa16(d, s);                                                  \
            }                                                                 \
        }                                                                     \
        const float* ws = kb + (size_t)_c*W_SZ;                               \
        for (int u = tid; u < W_SZ/4; u += 256)                               \
            cpa16(w_base[buf] + u*16, ws + u*4);                              \
        CP_COMMIT();                                                          \
    } while (0)

    unsigned long long acc[4][7];
    #pragma unroll
    for (int i = 0; i < 4; i++)
        #pragma unroll
        for (int p = 0; p < 7; p++) acc[i][p] = 0ULL;

    STAGE(0, 0);

    for (int k = 0; k < NCH; k++) {
        int cur = k & 1;
        if (k + 1 < NCH) { STAGE(k + 1, cur ^ 1); CP_WAIT1(); }
        else            { CP_WAIT0(); }
        __syncthreads();

        const float* inb = &in_s[cur][0];
        const float* wsb = &w_s[cur][0];

        #pragma unroll 2
        for (int ci = 0; ci < CIC; ci++) {
            #pragma unroll
            for (int ky = 0; ky < 3; ky++) {
                const float* ir = inb + ci*(IN_H*IN_W) + (row+ky)*IN_W + 3 + colb;
                unsigned long long xd[9];
                #pragma unroll
                for (int d2 = 0; d2 < 9; d2++) {
                    float xv = ir[d2];
                    xd[d2] = pk2(xv, xv);
                }
                #pragma unroll
                for (int kx = 0; kx < 3; kx++) {
                    int j = ci*9 + ky*3 + kx;
                    // warp-uniform float4 pair -> broadcast LDS.128
                    const float4 wa = *(const float4*)(wsb + j*OCT + warp*8);
                    const float4 wb = *(const float4*)(wsb + j*OCT + warp*8 + 4);
                    unsigned long long wp0 = pk2(wa.x, wa.y);
                    unsigned long long wp1 = pk2(wa.z, wa.w);
                    unsigned long long wp2 = pk2(wb.x, wb.y);
                    unsigned long long wp3 = pk2(wb.z, wb.w);
                    #pragma unroll
                    for (int p = 0; p < 7; p++) {
                        ffma2(acc[0][p], wp0, xd[p+kx]);
                        ffma2(acc[1][p], wp1, xd[p+kx]);
                        ffma2(acc[2][p], wp2, xd[p+kx]);
                        ffma2(acc[3][p], wp3, xd[p+kx]);
                    }
                }
            }
        }
        __syncthreads();   // protect buffer reuse by next iteration's STAGE
    }

    // ---- epilogue: unpack pairs, scatter per oc
    int orow = r0 + row;
    float* ob = out + ((size_t)b*COUT + oc0 + warp*8)*SPAT + orow*HW + colb;
    #pragma unroll
    for (int pr = 0; pr < 4; pr++) {
        #pragma unroll
        for (int p = 0; p < 7; p++) {
            float a0, a1;
            upk2(acc[pr][p], a0, a1);
            ob[(size_t)(2*pr  )*SPAT + p] = a0;
            ob[(size_t)(2*pr+1)*SPAT + p] = a1;
        }
    }
    #undef STAGE
}

// ============================================================
extern "C" void kernel_launch(void* const* d_in, const int* in_sizes, int n_in,
                              void* d_out, int out_size)
{
    const float* x     = (const float*)d_in[0];   // [32,128,56,56]
    const float* convs = (const float*)d_in[1];   // [4,256,128,3,3]
    const float* w1    = (const float*)d_in[2];   // [16,128]
    const float* b1    = (const float*)d_in[3];   // [16]
    const float* w2    = (const float*)d_in[4];   // [4,16]
    const float* b2    = (const float*)d_in[5];   // [4]
    float* out = (float*)d_out;                   // [32,256,56,56]

    router_kernel<<<B_, 256>>>(x, w1, b1, w2, b2);
    mix_kernel<<<dim3(NCH, COUT/OCT, B_), 256>>>(convs);
    dyconv_kernel<<<dim3(COUT/OCT, HW/RT, B_), 256>>>(x, out);
}